// round 8
// baseline (speedup 1.0000x reference)
#include <cuda_runtime.h>
#include <cuda_bf16.h>

// Persistent kernel, 5 blocks/SM budget (51 regs), grid = 6*148 (work-stealing
// flat region: >=40 warps/SM is perf-flat for this kernel).
// 8 edges per warp-chunk, 8-lane groups, 2 edges per group.
// Changes vs R7:
//  - feature gathers use __ldcg (L2-only, no L1 allocation) to avoid the
//    L1 fill pass on guaranteed-miss random gathers
//  - index broadcasts via per-lane scalar loads (same addr within group ->
//    broadcast wavefront) instead of LDG+4xSHFL; removes the shfl dependency
//    at the head of each chunk
//  - next chunk's 4 index loads prefetched before current chunk's gathers
__global__ void __launch_bounds__(256, 5) edge_dot_kernel(
    const float* __restrict__ h,
    const int* __restrict__ src,
    const int* __restrict__ dst,
    float* __restrict__ out,
    int n_edges)
{
    const int wib  = threadIdx.x >> 5;
    const int lane = threadIdx.x & 31;
    const int g = lane >> 3;        // group (0..3)
    const int t = lane & 7;         // sublane in group
    const unsigned FULL = 0xFFFFFFFFu;

    const int W = blockIdx.x * 8 + wib;       // global warp id
    const int stride = gridDim.x * 64;        // edges per sweep

    int e0 = W * 8;
    if (e0 >= n_edges) return;

    const int nm1 = n_edges - 1;

    // indices for first chunk: every lane loads its group's 4 indices
    int eA = e0 + 2 * g;
    int eB = min(eA + 1, nm1);
    int sA = __ldg(src + min(eA, nm1));
    int sB = __ldg(src + eB);
    int dA = __ldg(dst + min(eA, nm1));
    int dB = __ldg(dst + eB);

    while (true) {
        // ---- prefetch next chunk's indices
        int e0n = e0 + stride;
        int sA2 = 0, sB2 = 0, dA2 = 0, dB2 = 0;
        if (e0n < n_edges) {
            int a  = e0n + 2 * g;
            int a1 = min(a + 1, nm1);
            a = min(a, nm1);
            sA2 = __ldg(src + a);
            sB2 = __ldg(src + a1);
            dA2 = __ldg(dst + a);
            dB2 = __ldg(dst + a1);
        }

        // ---- current chunk gathers (L2-only streaming loads)
        const float4* psA = reinterpret_cast<const float4*>(h) + (size_t)sA * 32 + t;
        const float4* pdA = reinterpret_cast<const float4*>(h) + (size_t)dA * 32 + t;
        const float4* psB = reinterpret_cast<const float4*>(h) + (size_t)sB * 32 + t;
        const float4* pdB = reinterpret_cast<const float4*>(h) + (size_t)dB * 32 + t;

        float4 a0 = __ldcg(psA);      float4 a1 = __ldcg(psA + 8);
        float4 a2 = __ldcg(psA + 16); float4 a3 = __ldcg(psA + 24);
        float4 b0 = __ldcg(pdA);      float4 b1 = __ldcg(pdA + 8);
        float4 b2 = __ldcg(pdA + 16); float4 b3 = __ldcg(pdA + 24);
        float4 c0 = __ldcg(psB);      float4 c1 = __ldcg(psB + 8);
        float4 c2 = __ldcg(psB + 16); float4 c3 = __ldcg(psB + 24);
        float4 f0 = __ldcg(pdB);      float4 f1 = __ldcg(pdB + 8);
        float4 f2 = __ldcg(pdB + 16); float4 f3 = __ldcg(pdB + 24);

        float accA = a0.x * b0.x;
        accA = fmaf(a0.y, b0.y, accA); accA = fmaf(a0.z, b0.z, accA); accA = fmaf(a0.w, b0.w, accA);
        accA = fmaf(a1.x, b1.x, accA); accA = fmaf(a1.y, b1.y, accA);
        accA = fmaf(a1.z, b1.z, accA); accA = fmaf(a1.w, b1.w, accA);
        accA = fmaf(a2.x, b2.x, accA); accA = fmaf(a2.y, b2.y, accA);
        accA = fmaf(a2.z, b2.z, accA); accA = fmaf(a2.w, b2.w, accA);
        accA = fmaf(a3.x, b3.x, accA); accA = fmaf(a3.y, b3.y, accA);
        accA = fmaf(a3.z, b3.z, accA); accA = fmaf(a3.w, b3.w, accA);

        float accB = c0.x * f0.x;
        accB = fmaf(c0.y, f0.y, accB); accB = fmaf(c0.z, f0.z, accB); accB = fmaf(c0.w, f0.w, accB);
        accB = fmaf(c1.x, f1.x, accB); accB = fmaf(c1.y, f1.y, accB);
        accB = fmaf(c1.z, f1.z, accB); accB = fmaf(c1.w, f1.w, accB);
        accB = fmaf(c2.x, f2.x, accB); accB = fmaf(c2.y, f2.y, accB);
        accB = fmaf(c2.z, f2.z, accB); accB = fmaf(c2.w, f2.w, accB);
        accB = fmaf(c3.x, f3.x, accB); accB = fmaf(c3.y, f3.y, accB);
        accB = fmaf(c3.z, f3.z, accB); accB = fmaf(c3.w, f3.w, accB);

        // 3-level butterfly within the 8-lane group (4 edges reduced at once)
        accA += __shfl_xor_sync(FULL, accA, 4);
        accB += __shfl_xor_sync(FULL, accB, 4);
        accA += __shfl_xor_sync(FULL, accA, 2);
        accB += __shfl_xor_sync(FULL, accB, 2);
        accA += __shfl_xor_sync(FULL, accA, 1);
        accB += __shfl_xor_sync(FULL, accB, 1);

        if (t == 0) {
            int ea = e0 + 2 * g;
            if (ea + 1 < n_edges) {
                *reinterpret_cast<float2*>(out + ea) = make_float2(accA, accB);
            } else if (ea < n_edges) {
                out[ea] = accA;
            }
        }

        if (e0n >= n_edges) break;
        e0 = e0n;
        sA = sA2; sB = sB2; dA = dA2; dB = dB2;
    }
}

extern "C" void kernel_launch(void* const* d_in, const int* in_sizes, int n_in,
                              void* d_out, int out_size)
{
    const float* h   = (const float*)d_in[0];
    const int*   src = (const int*)d_in[1];
    const int*   dst = (const int*)d_in[2];
    float* out = (float*)d_out;

    int n_edges = in_sizes[1];               // E = 640000

    int grid = 6 * 148;                      // persistent sweep
    int max_grid = (n_edges + 63) / 64;      // every warp gets >=1 chunk
    if (grid > max_grid) grid = max_grid;

    edge_dot_kernel<<<grid, 256>>>(h, src, dst, out, n_edges);
}